// round 9
// baseline (speedup 1.0000x reference)
#include <cuda_runtime.h>
#include <cstdint>

#define HH 19
#define CELLS 361
#define MASK19 0x7FFFFu
#define BPB 8
#define NT 640                // 20 warps
#define NWARP 20
#define NBITW 200             // raw ballot chunks (20 warps x 10 iters)
#define FULLM 0xFFFFFFFFu
#define ONEF  0x3F800000u
#define TWOF  0x40000000u
#define FOURF 0x40800000u

// weak = opp stone with exactly one orthogonal opp neighbor
__device__ __forceinline__ uint32_t weak_row(uint32_t om, uint32_t ou, uint32_t od) {
    const uint32_t ol  = (om << 1) & MASK19;
    const uint32_t orr = om >> 1;
    const uint32_t par = ou ^ od ^ ol ^ orr;
    const uint32_t ge2 = (ou & od) | (ol & orr) | ((ou | od) & (ol | orr));
    return om & par & ~ge2;
}

// aligned 32-bit word w (bits [32w,32w+32)) of the 361-bit stream of 19 row masks
__device__ __forceinline__ uint32_t gather_word(const uint32_t* rm, int w) {
    uint32_t v = 0u;
    int r = (32 * w) / HH;
#pragma unroll
    for (int it = 0; it < 3; ++it) {
        if (r < HH) {
            const int sh = HH * r - 32 * w;
            if (sh < 32) {
                v |= (sh >= 0) ? (rm[r] << sh) : (rm[r] >> (-sh));
                ++r;
            }
        }
    }
    return v;
}

// bit `pos` of w as masked float bit-pattern (no I2F)
__device__ __forceinline__ uint32_t sextbit(uint32_t w, int pos, uint32_t K) {
    return (uint32_t)(((int32_t)(w << (31 - pos))) >> 31) & K;
}

// shift my stream word left across lanes by a: S'[lane] = funnelshift_l(stream[lane-1], stream[lane], a)
__device__ __forceinline__ uint32_t shift_stream(uint32_t myw, int a, int lane) {
    uint32_t prev = __shfl_up_sync(FULLM, myw, 1);
    if (lane == 0) prev = 0u;
    return __funnelshift_l(prev, myw, (unsigned)a);
}

__global__ __launch_bounds__(NT, 3)
void go_feat_kernel(const float* __restrict__ stones,
                    const int*   __restrict__ cur_player,
                    const int*   __restrict__ ko_points,
                    float*       __restrict__ out,
                    int B)
{
    __shared__ uint32_t s_bits[NBITW + 1];    // input bitstream pre-shifted by a_in
    __shared__ uint32_t s_cur[BPB][23];       // pad-2 row masks (real rows at [2..20])
    __shared__ uint32_t s_opp[BPB][23];
    __shared__ uint32_t s_emp[BPB][23];
    __shared__ uint32_t s_rm[4][BPB][HH];     // 0=legal, 1=b0, 2=b1, 3=b2
    __shared__ int      s_cp[BPB];
    __shared__ float    s_turn[BPB];
    __shared__ int      s_ko[BPB][2];

    const int t     = threadIdx.x;
    const int lane  = t & 31;
    const int warp  = t >> 5;
    const int bbase = blockIdx.x * BPB;
    const int rb    = (B - bbase) < BPB ? (B - bbase) : BPB;
    const int nin   = rb * 722;

    if (t < BPB) {
        const bool ok = t < rb;
        const int  b  = bbase + (ok ? t : 0);
        const int  cp = ok ? cur_player[b] : 0;
        s_cp[t]    = cp;
        s_turn[t]  = (float)cp;
        s_ko[t][0] = ok ? ko_points[2 * b]     : -1;
        s_ko[t][1] = ok ? ko_points[2 * b + 1] : 0;
    }

    // ---- Phase A: aligned-window ballot pack ----
    // element e = 32*chunk + lane - a_in ; raw ballot = input bits shifted by +a_in
    const size_t inbase = (size_t)bbase * 722;
    const int a_in = (int)(inbase & 31);
    const float* src_al = stones + (inbase - (size_t)a_in);   // 128B-aligned
#pragma unroll
    for (int k = 0; k < 10; ++k) {            // chunks 0..199 cover all needed bits
        const int c = k * NWARP + warp;
        const int e = (c << 5) + lane - a_in;
        const bool act = (unsigned)e < (unsigned)nin;
        float v = 0.0f;
        if (act) v = src_al[(c << 5) + lane];
        const unsigned bal = __ballot_sync(FULLM, act && (v > 0.5f));
        if (lane == 0) s_bits[c] = bal;
    }
    __syncthreads();

    // ---- Phase 1: row masks (bit offsets shifted by a_in) ----
    if (t < BPB * HH) {
        const int lb = t / HH, r = t % HH;
        const int bit0 = a_in + lb * 722 + r * HH;
        const int bit1 = bit0 + 361;
        const uint32_t m0 = __funnelshift_r(s_bits[bit0 >> 5], s_bits[(bit0 >> 5) + 1],
                                            bit0 & 31) & MASK19;
        const uint32_t m1 = __funnelshift_r(s_bits[bit1 >> 5], s_bits[(bit1 >> 5) + 1],
                                            bit1 & 31) & MASK19;
        const int cp = s_cp[lb];
        s_cur[lb][r + 2] = cp ? m1 : m0;
        s_opp[lb][r + 2] = cp ? m0 : m1;
        s_emp[lb][r + 2] = (~(m0 | m1)) & MASK19;
        if (r == 0) {
            s_cur[lb][0] = 0u; s_cur[lb][1] = 0u; s_cur[lb][21] = 0u; s_cur[lb][22] = 0u;
            s_opp[lb][0] = 0u; s_opp[lb][1] = 0u; s_opp[lb][21] = 0u; s_opp[lb][22] = 0u;
            s_emp[lb][0] = 0u; s_emp[lb][1] = 0u; s_emp[lb][21] = 0u; s_emp[lb][22] = 0u;
        }
    }
    __syncthreads();

    // ---- Phase 3: legal row masks (weak inlined) + liberty bitplanes ----
    if (t < 2 * BPB * HH) {
        const int half = t / (BPB * HH);
        const int w    = t % (BPB * HH);
        const int lb   = w / HH, r = w % HH;
        if (half == 0) {
            const uint32_t* op = s_opp[lb];
            const uint32_t wkm = weak_row(op[r + 2], op[r + 1], op[r + 3]);
            const uint32_t wku = weak_row(op[r + 1], op[r],     op[r + 2]);
            const uint32_t wkd = weak_row(op[r + 3], op[r + 2], op[r + 4]);
            const uint32_t empb = s_emp[lb][r + 2];
            const uint32_t eu = s_emp[lb][r + 1], ed = s_emp[lb][r + 3];
            const uint32_t nbr = eu | ed | ((empb << 1) & MASK19) | (empb >> 1)
                               | wku | wkd | ((wkm << 1) & MASK19) | (wkm >> 1);
            uint32_t legal = empb & nbr;
            const int kr = s_ko[lb][0];
            if (kr >= 0) {
                const int rr = kr > (HH - 1) ? (HH - 1) : kr;
                int cc = s_ko[lb][1];
                cc = cc < 0 ? 0 : (cc > (HH - 1) ? (HH - 1) : cc);
                if (rr == r) legal &= ~(1u << cc);
            }
            s_rm[0][lb][r] = legal;
        } else {
            const uint32_t curb = s_cur[lb][r + 2];
            const uint32_t cu   = s_cur[lb][r + 1];
            const uint32_t cd   = s_cur[lb][r + 3];
            const uint32_t cl   = (curb << 1) & MASK19;
            const uint32_t crr  = curb >> 1;
            const uint32_t empb = s_emp[lb][r + 2];
            const uint32_t sab = cu ^ cd,  cab = cu & cd;
            const uint32_t scd = cl ^ crr, ccd = cl & crr;
            const uint32_t kk  = sab & scd;
            s_rm[1][lb][r] = (sab ^ scd)      & empb;
            s_rm[2][lb][r] = (cab ^ ccd ^ kk) & empb;
            s_rm[3][lb][r] = (cab & ccd)      & empb;
        }
    }
    __syncthreads();

    // ---- Phase 4: warp-per-(board,channel), true aligned 128B store windows ----
#pragma unroll
    for (int u = warp; u < 5 * BPB; u += NWARP) {   // 2 units per warp
        const int lb = u / 5;
        const int ch = u - 5 * lb;
        if (lb >= rb) continue;                      // warp-uniform

        const size_t gbase = (size_t)bbase * 1805 + (size_t)(lb * 1805 + ch * CELLS);
        const int a = (int)(gbase & 31);
        float* o_al = out + (gbase - (size_t)a);     // 128B-aligned window base

        if (ch == 4) {
            const float tv = s_turn[lb];
#pragma unroll
            for (int it = 0; it < 13; ++it) {
                const int idx = it * 32 + lane;
                if ((unsigned)(idx - a) < (unsigned)CELLS) o_al[idx] = tv;
            }
        } else if (ch == 3) {
            uint32_t w0 = 0u, w1 = 0u, w2 = 0u;
            if (lane < 12) {
                w0 = gather_word(s_rm[1][lb], lane);
                w1 = gather_word(s_rm[2][lb], lane);
                w2 = gather_word(s_rm[3][lb], lane);
            }
            w0 = shift_stream(w0, a, lane);          // S' valid at lanes 0..12
            w1 = shift_stream(w1, a, lane);
            w2 = shift_stream(w2, a, lane);
#pragma unroll
            for (int it = 0; it < 13; ++it) {
                const uint32_t aw = __shfl_sync(FULLM, w0, it);
                const uint32_t bw = __shfl_sync(FULLM, w1, it);
                const uint32_t cw = __shfl_sync(FULLM, w2, it);
                const int idx = it * 32 + lane;
                const float f = __uint_as_float(sextbit(aw, lane, ONEF))
                              + __uint_as_float(sextbit(bw, lane, TWOF))
                              + __uint_as_float(sextbit(cw, lane, FOURF));
                if ((unsigned)(idx - a) < (unsigned)CELLS) o_al[idx] = f;
            }
        } else {
            uint32_t myw = 0u;
            if (lane < 12) {
                if (ch == 2) {
                    myw = gather_word(s_rm[0][lb], lane);
                } else {
                    const int pl   = (ch == 0) ? s_cp[lb] : 1 - s_cp[lb];
                    const int base = a_in + lb * 722 + pl * CELLS + 32 * lane;
                    myw = __funnelshift_r(s_bits[base >> 5], s_bits[(base >> 5) + 1],
                                          base & 31);
                }
            }
            myw = shift_stream(myw, a, lane);
#pragma unroll
            for (int it = 0; it < 13; ++it) {
                const uint32_t w = __shfl_sync(FULLM, myw, it);
                const int idx = it * 32 + lane;
                if ((unsigned)(idx - a) < (unsigned)CELLS)
                    o_al[idx] = __uint_as_float(sextbit(w, lane, ONEF));
            }
        }
    }
}

extern "C" void kernel_launch(void* const* d_in, const int* in_sizes, int n_in,
                              void* d_out, int out_size)
{
    const float* stones     = (const float*)d_in[0];
    const int*   cur_player = (const int*)  d_in[1];
    const int*   ko_points  = (const int*)  d_in[2];
    float*       out        = (float*)      d_out;

    const int B = in_sizes[1];
    const int grid = (B + BPB - 1) / BPB;
    go_feat_kernel<<<grid, NT>>>(stones, cur_player, ko_points, out, B);
}

// round 10
// speedup vs baseline: 1.1487x; 1.1487x over previous
#include <cuda_runtime.h>
#include <cstdint>

#define HH 19
#define CELLS 361
#define MASK19 0x7FFFFu
#define BPB 8
#define NT 640                // 20 warps
#define NWARP 20
#define NBITW 201             // ballot words (max idx 199) + funnel pad
#define FULLM 0xFFFFFFFFu

#define ONEF   0x3F800000u   // 1.0f
#define ONEF_2 0x1FC00000u   // *2 -> 1.0f
#define ONEF_4 0x0FE00000u   // *4 -> 1.0f
#define ONEF_8 0x07F00000u   // *8 -> 1.0f
#define TWOF   0x40000000u   // 2.0f
#define TWOF_2 0x20000000u
#define TWOF_4 0x10000000u
#define TWOF_8 0x08000000u
#define FOURF   0x40800000u  // 4.0f
#define FOURF_2 0x20400000u
#define FOURF_4 0x10200000u
#define FOURF_8 0x08100000u

// weak = opp stone with exactly one orthogonal opp neighbor
__device__ __forceinline__ uint32_t weak_row(uint32_t om, uint32_t ou, uint32_t od) {
    const uint32_t ol  = (om << 1) & MASK19;
    const uint32_t orr = om >> 1;
    const uint32_t par = ou ^ od ^ ol ^ orr;
    const uint32_t ge2 = (ou & od) | (ol & orr) | ((ou | od) & (ol | orr));
    return om & par & ~ge2;
}

// aligned 32-bit word w (bits [32w,32w+32)) of the 361-bit stream of 19 row masks
__device__ __forceinline__ uint32_t gather_word(const uint32_t* rm, int w) {
    uint32_t v = 0u;
    int r = (32 * w) / HH;
#pragma unroll
    for (int it = 0; it < 3; ++it) {
        if (r < HH) {
            const int sh = HH * r - 32 * w;
            if (sh < 32) {
                v |= (sh >= 0) ? (rm[r] << sh) : (rm[r] >> (-sh));
                ++r;
            }
        }
    }
    return v;
}

__global__ __launch_bounds__(NT, 3)
void go_feat_kernel(const float* __restrict__ stones,
                    const int*   __restrict__ cur_player,
                    const int*   __restrict__ ko_points,
                    float*       __restrict__ out,
                    int B)
{
    __shared__ uint32_t s_bits[NBITW];
    __shared__ uint32_t s_cur[BPB][23];       // pad-2 row masks (real rows at [2..20])
    __shared__ uint32_t s_opp[BPB][23];
    __shared__ uint32_t s_emp[BPB][23];
    __shared__ uint32_t s_rm[4][BPB][HH];     // 0=legal, 1=b0, 2=b1, 3=b2
    __shared__ int      s_cp[BPB];
    __shared__ float    s_turn[BPB];
    __shared__ int      s_ko[BPB][2];

    const int t     = threadIdx.x;
    const int lane  = t & 31;
    const int warp  = t >> 5;
    const int bbase = blockIdx.x * BPB;
    const int rb    = (B - bbase) < BPB ? (B - bbase) : BPB;
    const int nin   = rb * 722;

    if (t < BPB) {
        const bool ok = t < rb;
        const int  b  = bbase + (ok ? t : 0);
        const int  cp = ok ? cur_player[b] : 0;
        s_cp[t]    = cp;
        s_turn[t]  = (float)cp;
        s_ko[t][0] = ok ? ko_points[2 * b]     : -1;
        s_ko[t][1] = ok ? ko_points[2 * b + 1] : 0;
    }

    // ---- Phase A: ballot-pack input into bitstream (as R6) ----
    const float* src = stones + (size_t)bbase * 722;
#pragma unroll
    for (int k = 0; k < 10; ++k) {            // 10*640 = 6400 >= 5776
        const int i = k * NT + t;
        const bool act = i < nin;
        float v = 0.0f;
        if (act) v = src[i];
        const unsigned bal = __ballot_sync(FULLM, act && (v > 0.5f));
        if ((t & 31) == 0)
            s_bits[k * NWARP + (t >> 5)] = bal;
    }
    __syncthreads();

    // ---- Phase 1: row masks ----
    if (t < BPB * HH) {
        const int lb = t / HH, r = t % HH;
        const int bit0 = lb * 722 + r * HH;
        const int bit1 = bit0 + 361;
        const uint32_t m0 = __funnelshift_r(s_bits[bit0 >> 5], s_bits[(bit0 >> 5) + 1],
                                            bit0 & 31) & MASK19;
        const uint32_t m1 = __funnelshift_r(s_bits[bit1 >> 5], s_bits[(bit1 >> 5) + 1],
                                            bit1 & 31) & MASK19;
        const int cp = s_cp[lb];
        s_cur[lb][r + 2] = cp ? m1 : m0;
        s_opp[lb][r + 2] = cp ? m0 : m1;
        s_emp[lb][r + 2] = (~(m0 | m1)) & MASK19;
        if (r == 0) {
            s_cur[lb][0] = 0u; s_cur[lb][1] = 0u; s_cur[lb][21] = 0u; s_cur[lb][22] = 0u;
            s_opp[lb][0] = 0u; s_opp[lb][1] = 0u; s_opp[lb][21] = 0u; s_opp[lb][22] = 0u;
            s_emp[lb][0] = 0u; s_emp[lb][1] = 0u; s_emp[lb][21] = 0u; s_emp[lb][22] = 0u;
        }
    }
    __syncthreads();

    // ---- Phase 3: legal row masks (weak inlined) + liberty bitplanes ----
    if (t < 2 * BPB * HH) {
        const int half = t / (BPB * HH);
        const int w    = t % (BPB * HH);
        const int lb   = w / HH, r = w % HH;
        if (half == 0) {
            const uint32_t* op = s_opp[lb];
            const uint32_t wkm = weak_row(op[r + 2], op[r + 1], op[r + 3]);
            const uint32_t wku = weak_row(op[r + 1], op[r],     op[r + 2]);
            const uint32_t wkd = weak_row(op[r + 3], op[r + 2], op[r + 4]);
            const uint32_t empb = s_emp[lb][r + 2];
            const uint32_t eu = s_emp[lb][r + 1], ed = s_emp[lb][r + 3];
            const uint32_t nbr = eu | ed | ((empb << 1) & MASK19) | (empb >> 1)
                               | wku | wkd | ((wkm << 1) & MASK19) | (wkm >> 1);
            uint32_t legal = empb & nbr;
            const int kr = s_ko[lb][0];
            if (kr >= 0) {
                const int rr = kr > (HH - 1) ? (HH - 1) : kr;
                int cc = s_ko[lb][1];
                cc = cc < 0 ? 0 : (cc > (HH - 1) ? (HH - 1) : cc);
                if (rr == r) legal &= ~(1u << cc);
            }
            s_rm[0][lb][r] = legal;
        } else {
            const uint32_t curb = s_cur[lb][r + 2];
            const uint32_t cu   = s_cur[lb][r + 1];
            const uint32_t cd   = s_cur[lb][r + 3];
            const uint32_t cl   = (curb << 1) & MASK19;
            const uint32_t crr  = curb >> 1;
            const uint32_t empb = s_emp[lb][r + 2];
            const uint32_t sab = cu ^ cd,  cab = cu & cd;
            const uint32_t scd = cl ^ crr, ccd = cl & crr;
            const uint32_t kk  = sab & scd;
            s_rm[1][lb][r] = (sab ^ scd)      & empb;
            s_rm[2][lb][r] = (cab ^ ccd ^ kk) & empb;
            s_rm[3][lb][r] = (cab & ccd)      & empb;
        }
    }
    __syncthreads();

    // ---- Phase 4: warp-per-(board,channel), STG.128 nibble expansion ----
#pragma unroll
    for (int u = warp; u < 5 * BPB; u += NWARP) {   // 2 units per warp
        const int lb = u / 5;
        const int ch = u - 5 * lb;
        if (lb >= rb) continue;                      // warp-uniform

        const size_t gb = (size_t)bbase * 1805 + (size_t)(lb * 1805 + ch * CELLS);
        float* o = out + gb;
        const int s   = (int)((4u - ((uint32_t)gb & 3u)) & 3u);  // head scalars
        const int ng  = (CELLS - s) >> 2;                        // float4 groups
        const int tb  = s + 4 * ng;
        const int tc  = CELLS - tb;                              // tail scalars (0..3)
        float4* o4 = (float4*)(o + s);

        if (ch == 4) {
            const float tv = s_turn[lb];
            if (lane < s)  o[lane] = tv;
            if (lane < tc) o[tb + lane] = tv;
            const float4 v = make_float4(tv, tv, tv, tv);
#pragma unroll
            for (int it = 0; it < 3; ++it) {
                const int j = it * 32 + lane;
                if (j < ng) o4[j] = v;
            }
        } else if (ch == 3) {
            uint32_t w0 = 0u, w1 = 0u, w2 = 0u;
            if (lane < 12) {
                w0 = gather_word(s_rm[1][lb], lane);
                w1 = gather_word(s_rm[2][lb], lane);
                w2 = gather_word(s_rm[3][lb], lane);
            }
            const uint32_t h0 = __shfl_sync(FULLM, w0, 0);
            const uint32_t h1 = __shfl_sync(FULLM, w1, 0);
            const uint32_t h2 = __shfl_sync(FULLM, w2, 0);
            const uint32_t e0 = __shfl_sync(FULLM, w0, 11);
            const uint32_t e1 = __shfl_sync(FULLM, w1, 11);
            const uint32_t e2 = __shfl_sync(FULLM, w2, 11);
            if (lane < s) {
                const float f = __uint_as_float(((h0 >> lane) & 1u) * ONEF)
                              + __uint_as_float(((h1 >> lane) & 1u) * TWOF)
                              + __uint_as_float(((h2 >> lane) & 1u) * FOURF);
                o[lane] = f;
            }
            if (lane < tc) {
                const int sh = tb + lane - 352;
                const float f = __uint_as_float(((e0 >> sh) & 1u) * ONEF)
                              + __uint_as_float(((e1 >> sh) & 1u) * TWOF)
                              + __uint_as_float(((e2 >> sh) & 1u) * FOURF);
                o[tb + lane] = f;
            }
#pragma unroll
            for (int it = 0; it < 3; ++it) {
                const int j  = it * 32 + lane;
                const int bp = s + 4 * j;
                const int q  = bp >> 5, sh = bp & 31;
                const uint32_t p0 = __funnelshift_r(__shfl_sync(FULLM, w0, q),
                                                    __shfl_sync(FULLM, w0, q + 1), sh);
                const uint32_t p1 = __funnelshift_r(__shfl_sync(FULLM, w1, q),
                                                    __shfl_sync(FULLM, w1, q + 1), sh);
                const uint32_t p2 = __funnelshift_r(__shfl_sync(FULLM, w2, q),
                                                    __shfl_sync(FULLM, w2, q + 1), sh);
                float4 v;
                v.x = __uint_as_float((p0 & 1u) * ONEF)
                    + (__uint_as_float((p1 & 1u) * TWOF)
                     + __uint_as_float((p2 & 1u) * FOURF));
                v.y = __uint_as_float((p0 & 2u) * ONEF_2)
                    + (__uint_as_float((p1 & 2u) * TWOF_2)
                     + __uint_as_float((p2 & 2u) * FOURF_2));
                v.z = __uint_as_float((p0 & 4u) * ONEF_4)
                    + (__uint_as_float((p1 & 4u) * TWOF_4)
                     + __uint_as_float((p2 & 4u) * FOURF_4));
                v.w = __uint_as_float((p0 & 8u) * ONEF_8)
                    + (__uint_as_float((p1 & 8u) * TWOF_8)
                     + __uint_as_float((p2 & 8u) * FOURF_8));
                if (j < ng) o4[j] = v;
            }
        } else {
            uint32_t myw = 0u;
            if (lane < 12) {
                if (ch == 2) {
                    myw = gather_word(s_rm[0][lb], lane);
                } else {
                    const int pl   = (ch == 0) ? s_cp[lb] : 1 - s_cp[lb];
                    const int base = lb * 722 + pl * CELLS + 32 * lane;
                    myw = __funnelshift_r(s_bits[base >> 5], s_bits[(base >> 5) + 1],
                                          base & 31);
                }
            }
            const uint32_t h = __shfl_sync(FULLM, myw, 0);
            const uint32_t e = __shfl_sync(FULLM, myw, 11);
            if (lane < s)
                o[lane] = __uint_as_float(((h >> lane) & 1u) * ONEF);
            if (lane < tc)
                o[tb + lane] = __uint_as_float(((e >> (tb + lane - 352)) & 1u) * ONEF);
#pragma unroll
            for (int it = 0; it < 3; ++it) {
                const int j  = it * 32 + lane;
                const int bp = s + 4 * j;
                const int q  = bp >> 5, sh = bp & 31;
                const uint32_t pr = __funnelshift_r(__shfl_sync(FULLM, myw, q),
                                                    __shfl_sync(FULLM, myw, q + 1), sh);
                float4 v;
                v.x = __uint_as_float((pr & 1u) * ONEF);
                v.y = __uint_as_float((pr & 2u) * ONEF_2);
                v.z = __uint_as_float((pr & 4u) * ONEF_4);
                v.w = __uint_as_float((pr & 8u) * ONEF_8);
                if (j < ng) o4[j] = v;
            }
        }
    }
}

extern "C" void kernel_launch(void* const* d_in, const int* in_sizes, int n_in,
                              void* d_out, int out_size)
{
    const float* stones     = (const float*)d_in[0];
    const int*   cur_player = (const int*)  d_in[1];
    const int*   ko_points  = (const int*)  d_in[2];
    float*       out        = (float*)      d_out;

    const int B = in_sizes[1];
    const int grid = (B + BPB - 1) / BPB;
    go_feat_kernel<<<grid, NT>>>(stones, cur_player, ko_points, out, B);
}

// round 11
// speedup vs baseline: 1.4246x; 1.2402x over previous
#include <cuda_runtime.h>
#include <cstdint>

#define HH 19
#define CELLS 361
#define MASK19 0x7FFFFu
#define NT 512
#define WPB 16                // warps (=boards) per block
#define FULLM 0xFFFFFFFFu

#define ONEF   0x3F800000u   // 1.0f
#define ONEF_2 0x1FC00000u   // *2 -> 1.0f
#define ONEF_4 0x0FE00000u   // *4 -> 1.0f
#define ONEF_8 0x07F00000u   // *8 -> 1.0f
#define TWOF   0x40000000u   // 2.0f
#define TWOF_2 0x20000000u
#define TWOF_4 0x10000000u
#define TWOF_8 0x08000000u
#define FOURF   0x40800000u  // 4.0f
#define FOURF_2 0x20400000u
#define FOURF_4 0x10200000u
#define FOURF_8 0x08100000u

// weak = opp stone with exactly one orthogonal opp neighbor
__device__ __forceinline__ uint32_t weak_row(uint32_t om, uint32_t ou, uint32_t od) {
    const uint32_t ol  = (om << 1) & MASK19;
    const uint32_t orr = om >> 1;
    const uint32_t par = ou ^ od ^ ol ^ orr;
    const uint32_t ge2 = (ou & od) | (ol & orr) | ((ou | od) & (ol | orr));
    return om & par & ~ge2;
}

// expand a 361-bit stream (word w in lane w, w=0..11) of 0/1 bits to floats
__device__ __forceinline__ void expand_binary(float* __restrict__ out,
                                              size_t gb, uint32_t S, int lane) {
    float* o = out + gb;
    const int s  = (int)((4u - ((uint32_t)gb & 3u)) & 3u);
    const int ng = (CELLS - s) >> 2;
    const int tb = s + 4 * ng;
    const int tc = CELLS - tb;
    float4* o4 = (float4*)(o + s);
    const uint32_t h = __shfl_sync(FULLM, S, 0);
    const uint32_t e = __shfl_sync(FULLM, S, 11);
    if (lane < s)  o[lane] = __uint_as_float(((h >> lane) & 1u) * ONEF);
    if (lane < tc) o[tb + lane] = __uint_as_float(((e >> (tb + lane - 352)) & 1u) * ONEF);
#pragma unroll
    for (int it = 0; it < 3; ++it) {
        const int j  = it * 32 + lane;
        const int bp = s + 4 * j;
        const int q  = bp >> 5, sh = bp & 31;
        const uint32_t pr = __funnelshift_r(__shfl_sync(FULLM, S, q),
                                            __shfl_sync(FULLM, S, (q + 1) & 31), sh);
        float4 v;
        v.x = __uint_as_float((pr & 1u) * ONEF);
        v.y = __uint_as_float((pr & 2u) * ONEF_2);
        v.z = __uint_as_float((pr & 4u) * ONEF_4);
        v.w = __uint_as_float((pr & 8u) * ONEF_8);
        if (j < ng) o4[j] = v;
    }
}

__global__ __launch_bounds__(NT)
void go_feat_kernel(const float* __restrict__ stones,
                    const int*   __restrict__ cur_player,
                    const int*   __restrict__ ko_points,
                    float*       __restrict__ out,
                    int B)
{
    const int lane = threadIdx.x & 31;
    const int b    = blockIdx.x * WPB + (threadIdx.x >> 5);
    if (b >= B) return;                       // warp-uniform

    const int cp = cur_player[b];             // broadcast loads (same addr per warp)
    const int kr = ko_points[2 * b];
    const int kc = ko_points[2 * b + 1];

    // ---- 1: ballot-pack the board's 722 floats; word k parked in lane k ----
    const float* src = stones + (size_t)b * 722;
    uint32_t W = 0u;
#pragma unroll
    for (int k = 0; k < 23; ++k) {
        const int e = (k << 5) + lane;
        float v = 0.0f;
        if (e < 722) v = src[e];
        const unsigned bal = __ballot_sync(FULLM, v > 0.5f);
        if (lane == k) W = bal;
    }

    // ---- 2: row masks; lane r = row r (lanes >= 19 forced to 0) ----
    const int bit0 = HH * lane;
    const uint32_t m0 = __funnelshift_r(__shfl_sync(FULLM, W, (bit0 >> 5) & 31),
                                        __shfl_sync(FULLM, W, ((bit0 >> 5) + 1) & 31),
                                        bit0) & MASK19;
    const int bit1 = bit0 + CELLS;
    const uint32_t m1 = __funnelshift_r(__shfl_sync(FULLM, W, (bit1 >> 5) & 31),
                                        __shfl_sync(FULLM, W, ((bit1 >> 5) + 1) & 31),
                                        bit1) & MASK19;
    const bool rowok = lane < HH;
    const uint32_t curb = rowok ? (cp ? m1 : m0) : 0u;
    const uint32_t oppb = rowok ? (cp ? m0 : m1) : 0u;
    const uint32_t empb = rowok ? ((~(m0 | m1)) & MASK19) : 0u;

    // ---- 3: stencils, lane-parallel (wrap-around shfl hits zeroed lanes) ----
    const uint32_t ou = __shfl_sync(FULLM, oppb, (lane - 1) & 31);
    const uint32_t od = __shfl_sync(FULLM, oppb, (lane + 1) & 31);
    const uint32_t wk  = weak_row(oppb, ou, od);
    const uint32_t wku = __shfl_sync(FULLM, wk, (lane - 1) & 31);
    const uint32_t wkd = __shfl_sync(FULLM, wk, (lane + 1) & 31);
    const uint32_t eu = __shfl_sync(FULLM, empb, (lane - 1) & 31);
    const uint32_t ed = __shfl_sync(FULLM, empb, (lane + 1) & 31);

    uint32_t legal = empb & (eu | ed | ((empb << 1) & MASK19) | (empb >> 1)
                   | wku | wkd | ((wk << 1) & MASK19) | (wk >> 1));
    if (kr >= 0) {
        const int rr = kr > (HH - 1) ? (HH - 1) : kr;
        int cc = kc < 0 ? 0 : (kc > (HH - 1) ? (HH - 1) : kc);
        if (lane == rr) legal &= ~(1u << cc);
    }

    const uint32_t cu = __shfl_sync(FULLM, curb, (lane - 1) & 31);
    const uint32_t cd = __shfl_sync(FULLM, curb, (lane + 1) & 31);
    const uint32_t cl = (curb << 1) & MASK19;
    const uint32_t cr = curb >> 1;
    const uint32_t sab = cu ^ cd,  cab = cu & cd;
    const uint32_t scd = cl ^ cr,  ccd = cl & cr;
    const uint32_t kx  = sab & scd;
    const uint32_t p0 = (sab ^ scd)      & empb;   // ones
    const uint32_t p1 = (cab ^ ccd ^ kx) & empb;   // twos
    const uint32_t p2 = (cab & ccd)      & empb;   // fours

    // ---- 4: build 361-bit streams (word w in lane w, w = 0..11) ----
    const int w32 = lane << 5;
    const int r0  = w32 / HH;
    uint32_t ls = 0u, a0 = 0u, a1 = 0u, a2 = 0u;
#pragma unroll
    for (int i = 0; i < 3; ++i) {
        const int r  = r0 + i;
        const int sh = HH * r - w32;               // (-19, 39)
        const uint32_t lm = __shfl_sync(FULLM, legal, r & 31);
        const uint32_t q0 = __shfl_sync(FULLM, p0,    r & 31);
        const uint32_t q1 = __shfl_sync(FULLM, p1,    r & 31);
        const uint32_t q2 = __shfl_sync(FULLM, p2,    r & 31);
        if (sh >= 0) {
            if (sh < 32) {
                ls |= lm << sh; a0 |= q0 << sh; a1 |= q1 << sh; a2 |= q2 << sh;
            }
        } else {
            ls |= lm >> (-sh); a0 |= q0 >> (-sh); a1 |= q1 >> (-sh); a2 |= q2 >> (-sh);
        }
    }
    // cur/opp streams come free from the packed input bits
    const int pbase = cp * CELLS + w32;
    const uint32_t cur_s = __funnelshift_r(__shfl_sync(FULLM, W, (pbase >> 5) & 31),
                                           __shfl_sync(FULLM, W, ((pbase >> 5) + 1) & 31),
                                           pbase);
    const int obase = (1 - cp) * CELLS + w32;
    const uint32_t opp_s = __funnelshift_r(__shfl_sync(FULLM, W, (obase >> 5) & 31),
                                           __shfl_sync(FULLM, W, ((obase >> 5) + 1) & 31),
                                           obase);

    // ---- 5: expansion, 5 channels ----
    const size_t gb0 = (size_t)b * 1805;
    expand_binary(out, gb0,             cur_s, lane);
    expand_binary(out, gb0 + CELLS,     opp_s, lane);
    expand_binary(out, gb0 + 2 * CELLS, ls,    lane);

    {   // ch3: liberties (0..7, exact)
        const size_t gb = gb0 + 3 * CELLS;
        float* o = out + gb;
        const int s  = (int)((4u - ((uint32_t)gb & 3u)) & 3u);
        const int ng = (CELLS - s) >> 2;
        const int tb = s + 4 * ng;
        const int tc = CELLS - tb;
        float4* o4 = (float4*)(o + s);
        const uint32_t h0 = __shfl_sync(FULLM, a0, 0);
        const uint32_t h1 = __shfl_sync(FULLM, a1, 0);
        const uint32_t h2 = __shfl_sync(FULLM, a2, 0);
        const uint32_t e0 = __shfl_sync(FULLM, a0, 11);
        const uint32_t e1 = __shfl_sync(FULLM, a1, 11);
        const uint32_t e2 = __shfl_sync(FULLM, a2, 11);
        if (lane < s) {
            o[lane] = __uint_as_float(((h0 >> lane) & 1u) * ONEF)
                    + __uint_as_float(((h1 >> lane) & 1u) * TWOF)
                    + __uint_as_float(((h2 >> lane) & 1u) * FOURF);
        }
        if (lane < tc) {
            const int sh = tb + lane - 352;
            o[tb + lane] = __uint_as_float(((e0 >> sh) & 1u) * ONEF)
                         + __uint_as_float(((e1 >> sh) & 1u) * TWOF)
                         + __uint_as_float(((e2 >> sh) & 1u) * FOURF);
        }
#pragma unroll
        for (int it = 0; it < 3; ++it) {
            const int j  = it * 32 + lane;
            const int bp = s + 4 * j;
            const int q  = bp >> 5, sh = bp & 31;
            const uint32_t r0w = __funnelshift_r(__shfl_sync(FULLM, a0, q),
                                                 __shfl_sync(FULLM, a0, (q + 1) & 31), sh);
            const uint32_t r1w = __funnelshift_r(__shfl_sync(FULLM, a1, q),
                                                 __shfl_sync(FULLM, a1, (q + 1) & 31), sh);
            const uint32_t r2w = __funnelshift_r(__shfl_sync(FULLM, a2, q),
                                                 __shfl_sync(FULLM, a2, (q + 1) & 31), sh);
            float4 v;
            v.x = __uint_as_float((r0w & 1u) * ONEF)
                + (__uint_as_float((r1w & 1u) * TWOF)
                 + __uint_as_float((r2w & 1u) * FOURF));
            v.y = __uint_as_float((r0w & 2u) * ONEF_2)
                + (__uint_as_float((r1w & 2u) * TWOF_2)
                 + __uint_as_float((r2w & 2u) * FOURF_2));
            v.z = __uint_as_float((r0w & 4u) * ONEF_4)
                + (__uint_as_float((r1w & 4u) * TWOF_4)
                 + __uint_as_float((r2w & 4u) * FOURF_4));
            v.w = __uint_as_float((r0w & 8u) * ONEF_8)
                + (__uint_as_float((r1w & 8u) * TWOF_8)
                 + __uint_as_float((r2w & 8u) * FOURF_8));
            if (j < ng) o4[j] = v;
        }
    }

    {   // ch4: turn broadcast
        const size_t gb = gb0 + 4 * CELLS;
        float* o = out + gb;
        const int s  = (int)((4u - ((uint32_t)gb & 3u)) & 3u);
        const int ng = (CELLS - s) >> 2;
        const int tb = s + 4 * ng;
        const int tc = CELLS - tb;
        float4* o4 = (float4*)(o + s);
        const float tv = (float)cp;
        if (lane < s)  o[lane] = tv;
        if (lane < tc) o[tb + lane] = tv;
        const float4 v = make_float4(tv, tv, tv, tv);
#pragma unroll
        for (int it = 0; it < 3; ++it) {
            const int j = it * 32 + lane;
            if (j < ng) o4[j] = v;
        }
    }
}

extern "C" void kernel_launch(void* const* d_in, const int* in_sizes, int n_in,
                              void* d_out, int out_size)
{
    const float* stones     = (const float*)d_in[0];
    const int*   cur_player = (const int*)  d_in[1];
    const int*   ko_points  = (const int*)  d_in[2];
    float*       out        = (float*)      d_out;

    const int B = in_sizes[1];
    const int grid = (B + WPB - 1) / WPB;
    go_feat_kernel<<<grid, NT>>>(stones, cur_player, ko_points, out, B);
}

// round 12
// speedup vs baseline: 1.4349x; 1.0072x over previous
#include <cuda_runtime.h>
#include <cstdint>

#define HH 19
#define CELLS 361
#define MASK19 0x7FFFFu
#define NT 512
#define WPB 16                // warps (=boards) per block
#define FULLM 0xFFFFFFFFu

#define ONEF   0x3F800000u   // 1.0f
#define ONEF_2 0x1FC00000u   // *2 -> 1.0f
#define ONEF_4 0x0FE00000u   // *4 -> 1.0f
#define ONEF_8 0x07F00000u   // *8 -> 1.0f
#define TWOF   0x40000000u   // 2.0f
#define TWOF_2 0x20000000u
#define TWOF_4 0x10000000u
#define TWOF_8 0x08000000u
#define FOURF   0x40800000u  // 4.0f
#define FOURF_2 0x20400000u
#define FOURF_4 0x10200000u
#define FOURF_8 0x08100000u

// weak = opp stone with exactly one orthogonal opp neighbor
__device__ __forceinline__ uint32_t weak_row(uint32_t om, uint32_t ou, uint32_t od) {
    const uint32_t ol  = (om << 1) & MASK19;
    const uint32_t orr = om >> 1;
    const uint32_t par = ou ^ od ^ ol ^ orr;
    const uint32_t ge2 = (ou & od) | (ol & orr) | ((ou | od) & (ol | orr));
    return om & par & ~ge2;
}

// expand a 361-bit stream (word w in lane w, w=0..11) of 0/1 bits to floats
__device__ __forceinline__ void expand_binary(float* __restrict__ out,
                                              size_t gb, uint32_t S, int lane) {
    float* o = out + gb;
    const int s  = (int)((4u - ((uint32_t)gb & 3u)) & 3u);
    const int ng = (CELLS - s) >> 2;
    const int tb = s + 4 * ng;
    const int tc = CELLS - tb;
    float4* o4 = (float4*)(o + s);
    const uint32_t h = __shfl_sync(FULLM, S, 0);
    const uint32_t e = __shfl_sync(FULLM, S, 11);
    if (lane < s)  o[lane] = __uint_as_float(((h >> lane) & 1u) * ONEF);
    if (lane < tc) o[tb + lane] = __uint_as_float(((e >> (tb + lane - 352)) & 1u) * ONEF);
#pragma unroll
    for (int it = 0; it < 3; ++it) {
        const int j  = it * 32 + lane;
        const int bp = s + 4 * j;
        const int q  = bp >> 5, sh = bp & 31;
        const uint32_t pr = __funnelshift_r(__shfl_sync(FULLM, S, q),
                                            __shfl_sync(FULLM, S, (q + 1) & 31), sh);
        float4 v;
        v.x = __uint_as_float((pr & 1u) * ONEF);
        v.y = __uint_as_float((pr & 2u) * ONEF_2);
        v.z = __uint_as_float((pr & 4u) * ONEF_4);
        v.w = __uint_as_float((pr & 8u) * ONEF_8);
        if (j < ng) o4[j] = v;
    }
}

__global__ __launch_bounds__(NT, 2)
void go_feat_kernel(const float* __restrict__ stones,
                    const int*   __restrict__ cur_player,
                    const int*   __restrict__ ko_points,
                    float*       __restrict__ out,
                    int B)
{
    const int lane = threadIdx.x & 31;
    const int b    = blockIdx.x * WPB + (threadIdx.x >> 5);
    if (b >= B) return;                       // warp-uniform

    const int cp = cur_player[b];             // broadcast loads (same addr per warp)
    const int kr = ko_points[2 * b];
    const int kc = ko_points[2 * b + 1];

    // ---- 1: ballot-pack the board's 722 floats; word k parked in lane k ----
    // Two-pass: batch ALL loads first (MLP=23), then do the ballots.
    const float* src = stones + (size_t)b * 722;
    float vals[23];
#pragma unroll
    for (int k = 0; k < 23; ++k) {
        const int e = (k << 5) + lane;
        vals[k] = (e < 722) ? src[e] : 0.0f;
    }
    uint32_t W = 0u;
#pragma unroll
    for (int k = 0; k < 23; ++k) {
        const unsigned bal = __ballot_sync(FULLM, vals[k] > 0.5f);
        if (lane == k) W = bal;
    }

    // ---- 2: row masks; lane r = row r (lanes >= 19 forced to 0) ----
    const int bit0 = HH * lane;
    const uint32_t m0 = __funnelshift_r(__shfl_sync(FULLM, W, (bit0 >> 5) & 31),
                                        __shfl_sync(FULLM, W, ((bit0 >> 5) + 1) & 31),
                                        bit0) & MASK19;
    const int bit1 = bit0 + CELLS;
    const uint32_t m1 = __funnelshift_r(__shfl_sync(FULLM, W, (bit1 >> 5) & 31),
                                        __shfl_sync(FULLM, W, ((bit1 >> 5) + 1) & 31),
                                        bit1) & MASK19;
    const bool rowok = lane < HH;
    const uint32_t curb = rowok ? (cp ? m1 : m0) : 0u;
    const uint32_t oppb = rowok ? (cp ? m0 : m1) : 0u;
    const uint32_t empb = rowok ? ((~(m0 | m1)) & MASK19) : 0u;

    // ---- 3: stencils, lane-parallel (wrap-around shfl hits zeroed lanes) ----
    const uint32_t ou = __shfl_sync(FULLM, oppb, (lane - 1) & 31);
    const uint32_t od = __shfl_sync(FULLM, oppb, (lane + 1) & 31);
    const uint32_t wk  = weak_row(oppb, ou, od);
    const uint32_t wku = __shfl_sync(FULLM, wk, (lane - 1) & 31);
    const uint32_t wkd = __shfl_sync(FULLM, wk, (lane + 1) & 31);
    const uint32_t eu = __shfl_sync(FULLM, empb, (lane - 1) & 31);
    const uint32_t ed = __shfl_sync(FULLM, empb, (lane + 1) & 31);

    uint32_t legal = empb & (eu | ed | ((empb << 1) & MASK19) | (empb >> 1)
                   | wku | wkd | ((wk << 1) & MASK19) | (wk >> 1));
    if (kr >= 0) {
        const int rr = kr > (HH - 1) ? (HH - 1) : kr;
        int cc = kc < 0 ? 0 : (kc > (HH - 1) ? (HH - 1) : kc);
        if (lane == rr) legal &= ~(1u << cc);
    }

    const uint32_t cu = __shfl_sync(FULLM, curb, (lane - 1) & 31);
    const uint32_t cd = __shfl_sync(FULLM, curb, (lane + 1) & 31);
    const uint32_t cl = (curb << 1) & MASK19;
    const uint32_t cr = curb >> 1;
    const uint32_t sab = cu ^ cd,  cab = cu & cd;
    const uint32_t scd = cl ^ cr,  ccd = cl & cr;
    const uint32_t kx  = sab & scd;
    const uint32_t p0 = (sab ^ scd)      & empb;   // ones
    const uint32_t p1 = (cab ^ ccd ^ kx) & empb;   // twos
    const uint32_t p2 = (cab & ccd)      & empb;   // fours

    // ---- 4: build 361-bit streams (word w in lane w, w = 0..11) ----
    const int w32 = lane << 5;
    const int r0  = w32 / HH;
    uint32_t ls = 0u, a0 = 0u, a1 = 0u, a2 = 0u;
#pragma unroll
    for (int i = 0; i < 3; ++i) {
        const int r  = r0 + i;
        const int sh = HH * r - w32;               // (-19, 39)
        const uint32_t lm = __shfl_sync(FULLM, legal, r & 31);
        const uint32_t q0 = __shfl_sync(FULLM, p0,    r & 31);
        const uint32_t q1 = __shfl_sync(FULLM, p1,    r & 31);
        const uint32_t q2 = __shfl_sync(FULLM, p2,    r & 31);
        if (sh >= 0) {
            if (sh < 32) {
                ls |= lm << sh; a0 |= q0 << sh; a1 |= q1 << sh; a2 |= q2 << sh;
            }
        } else {
            ls |= lm >> (-sh); a0 |= q0 >> (-sh); a1 |= q1 >> (-sh); a2 |= q2 >> (-sh);
        }
    }
    // cur/opp streams come free from the packed input bits
    const int pbase = cp * CELLS + w32;
    const uint32_t cur_s = __funnelshift_r(__shfl_sync(FULLM, W, (pbase >> 5) & 31),
                                           __shfl_sync(FULLM, W, ((pbase >> 5) + 1) & 31),
                                           pbase);
    const int obase = (1 - cp) * CELLS + w32;
    const uint32_t opp_s = __funnelshift_r(__shfl_sync(FULLM, W, (obase >> 5) & 31),
                                           __shfl_sync(FULLM, W, ((obase >> 5) + 1) & 31),
                                           obase);

    // ---- 5: expansion, 5 channels ----
    const size_t gb0 = (size_t)b * 1805;
    expand_binary(out, gb0,             cur_s, lane);
    expand_binary(out, gb0 + CELLS,     opp_s, lane);
    expand_binary(out, gb0 + 2 * CELLS, ls,    lane);

    {   // ch3: liberties (0..7, exact)
        const size_t gb = gb0 + 3 * CELLS;
        float* o = out + gb;
        const int s  = (int)((4u - ((uint32_t)gb & 3u)) & 3u);
        const int ng = (CELLS - s) >> 2;
        const int tb = s + 4 * ng;
        const int tc = CELLS - tb;
        float4* o4 = (float4*)(o + s);
        const uint32_t h0 = __shfl_sync(FULLM, a0, 0);
        const uint32_t h1 = __shfl_sync(FULLM, a1, 0);
        const uint32_t h2 = __shfl_sync(FULLM, a2, 0);
        const uint32_t e0 = __shfl_sync(FULLM, a0, 11);
        const uint32_t e1 = __shfl_sync(FULLM, a1, 11);
        const uint32_t e2 = __shfl_sync(FULLM, a2, 11);
        if (lane < s) {
            o[lane] = __uint_as_float(((h0 >> lane) & 1u) * ONEF)
                    + __uint_as_float(((h1 >> lane) & 1u) * TWOF)
                    + __uint_as_float(((h2 >> lane) & 1u) * FOURF);
        }
        if (lane < tc) {
            const int sh = tb + lane - 352;
            o[tb + lane] = __uint_as_float(((e0 >> sh) & 1u) * ONEF)
                         + __uint_as_float(((e1 >> sh) & 1u) * TWOF)
                         + __uint_as_float(((e2 >> sh) & 1u) * FOURF);
        }
#pragma unroll
        for (int it = 0; it < 3; ++it) {
            const int j  = it * 32 + lane;
            const int bp = s + 4 * j;
            const int q  = bp >> 5, sh = bp & 31;
            const uint32_t r0w = __funnelshift_r(__shfl_sync(FULLM, a0, q),
                                                 __shfl_sync(FULLM, a0, (q + 1) & 31), sh);
            const uint32_t r1w = __funnelshift_r(__shfl_sync(FULLM, a1, q),
                                                 __shfl_sync(FULLM, a1, (q + 1) & 31), sh);
            const uint32_t r2w = __funnelshift_r(__shfl_sync(FULLM, a2, q),
                                                 __shfl_sync(FULLM, a2, (q + 1) & 31), sh);
            float4 v;
            v.x = __uint_as_float((r0w & 1u) * ONEF)
                + (__uint_as_float((r1w & 1u) * TWOF)
                 + __uint_as_float((r2w & 1u) * FOURF));
            v.y = __uint_as_float((r0w & 2u) * ONEF_2)
                + (__uint_as_float((r1w & 2u) * TWOF_2)
                 + __uint_as_float((r2w & 2u) * FOURF_2));
            v.z = __uint_as_float((r0w & 4u) * ONEF_4)
                + (__uint_as_float((r1w & 4u) * TWOF_4)
                 + __uint_as_float((r2w & 4u) * FOURF_4));
            v.w = __uint_as_float((r0w & 8u) * ONEF_8)
                + (__uint_as_float((r1w & 8u) * TWOF_8)
                 + __uint_as_float((r2w & 8u) * FOURF_8));
            if (j < ng) o4[j] = v;
        }
    }

    {   // ch4: turn broadcast
        const size_t gb = gb0 + 4 * CELLS;
        float* o = out + gb;
        const int s  = (int)((4u - ((uint32_t)gb & 3u)) & 3u);
        const int ng = (CELLS - s) >> 2;
        const int tb = s + 4 * ng;
        const int tc = CELLS - tb;
        float4* o4 = (float4*)(o + s);
        const float tv = (float)cp;
        if (lane < s)  o[lane] = tv;
        if (lane < tc) o[tb + lane] = tv;
        const float4 v = make_float4(tv, tv, tv, tv);
#pragma unroll
        for (int it = 0; it < 3; ++it) {
            const int j = it * 32 + lane;
            if (j < ng) o4[j] = v;
        }
    }
}

extern "C" void kernel_launch(void* const* d_in, const int* in_sizes, int n_in,
                              void* d_out, int out_size)
{
    const float* stones     = (const float*)d_in[0];
    const int*   cur_player = (const int*)  d_in[1];
    const int*   ko_points  = (const int*)  d_in[2];
    float*       out        = (float*)      d_out;

    const int B = in_sizes[1];
    const int grid = (B + WPB - 1) / WPB;
    go_feat_kernel<<<grid, NT>>>(stones, cur_player, ko_points, out, B);
}